// round 1
// baseline (speedup 1.0000x reference)
#include <cuda_runtime.h>
#include <cuda_bf16.h>
#include <math.h>

// Problem constants
#define Bq 4
#define Sq 8192
#define Dq 512
#define Hq 8
#define HDq 64
#define Mq (Bq * Sq)           // 32768 tokens
#define Nqkv (3 * Dq)          // 1536
#define Kq Dq                  // 512

// ---------------- scratch (static device memory; no allocations) ----------------
__device__ float g_q[(size_t)Mq * Dq];     // phi(q)          64MB
__device__ float g_k[(size_t)Mq * Dq];     // phi(k)*mask     64MB
__device__ float g_v[(size_t)Mq * Dq];     // v*mask          64MB
__device__ float g_attn[(size_t)Mq * Dq];  // attention out   64MB
__device__ float g_kv[Bq * Hq * HDq * HDq];   // 131072 floats
__device__ float g_ksum[Bq * Hq * HDq];       // 2048 floats
__device__ float g_mask[Mq];                  // 1.0 = keep, 0.0 = padded

// ---------------- mask dtype detection + canonicalization ----------------
// key_padding_mask comes from a jax bool array; the harness may hand it to us
// as uint8/bool, int32, or float32. Detect by word pattern, then write a
// canonical float keep-mask. True in the input means "ignore" -> keep = 0.
__global__ void mask_kernel(const void* __restrict__ mraw) {
    __shared__ int s_f32, s_big;
    if (threadIdx.x == 0) { s_f32 = 0; s_big = 0; }
    __syncthreads();
    const unsigned int* w = (const unsigned int*)mraw;
    int f32 = 0, big = 0;
    // first 8192 words = 32768 bytes, in-bounds for every candidate dtype
    for (int i = threadIdx.x; i < 8192; i += blockDim.x) {
        unsigned int x = w[i];
        if (x == 0x3F800000u) f32 = 1;
        else if (x > 1u) big = 1;
    }
    if (f32) atomicOr(&s_f32, 1);
    if (big) atomicOr(&s_big, 1);
    __syncthreads();
    // mode: 2 = float32, 0 = uint8/bool, 1 = int32
    int mode = s_f32 ? 2 : (s_big ? 0 : 1);
    for (int i = threadIdx.x; i < Mq; i += blockDim.x) {
        bool pad;
        if (mode == 0)      pad = ((const unsigned char*)mraw)[i] != 0;
        else if (mode == 1) pad = ((const int*)mraw)[i] != 0;
        else                pad = ((const float*)mraw)[i] != 0.0f;
        g_mask[i] = pad ? 0.0f : 1.0f;
    }
}

__global__ void zero_kv_kernel() {
    int i = blockIdx.x * blockDim.x + threadIdx.x;
    if (i < Bq * Hq * HDq * HDq) g_kv[i] = 0.0f;
    if (i < Bq * Hq * HDq) g_ksum[i] = 0.0f;
}

__device__ __forceinline__ float phi(float x) {
    // elu(x)+1 : x>0 ? x+1 : exp(x)
    return x > 0.0f ? x + 1.0f : expf(x);
}

// ---------------- generic GEMM: C[m][n] = sum_k A[m][k] * W[n][k] + bias[n] ----------------
// 128x128 tile, BK=8, 256 threads, 8x8 per thread (split as 2x2 quads of 4x4).
// mode 0: QKV epilogue (phi / mask, write g_q/g_k/g_v).  A = query.
// mode 1: plain epilogue to Cout.                         A = g_attn.
__global__ __launch_bounds__(256, 2)
void gemm_kernel(const float* __restrict__ Ain, const float* __restrict__ W,
                 const float* __restrict__ bias, float* __restrict__ Cout,
                 int mode) {
    const int K = Kq;
    const float* A = (mode == 1) ? (const float*)g_attn : Ain;

    __shared__ float As[8][128];
    __shared__ float Ws[8][128];

    const int tid = threadIdx.x;
    const int m0 = blockIdx.y * 128;
    const int n0 = blockIdx.x * 128;
    const int tx = tid & 15;
    const int ty = tid >> 4;

    float acc[8][8];
#pragma unroll
    for (int i = 0; i < 8; i++)
#pragma unroll
        for (int j = 0; j < 8; j++) acc[i][j] = 0.0f;

    const int lm = tid >> 1;          // 0..127
    const int lk = (tid & 1) * 4;     // 0 or 4
    const float* Aptr = A + (size_t)(m0 + lm) * K + lk;
    const float* Wptr = W + (size_t)(n0 + lm) * K + lk;

    for (int k0 = 0; k0 < K; k0 += 8) {
        float4 av = *(const float4*)(Aptr + k0);
        float4 wv = *(const float4*)(Wptr + k0);
        As[lk + 0][lm] = av.x; As[lk + 1][lm] = av.y;
        As[lk + 2][lm] = av.z; As[lk + 3][lm] = av.w;
        Ws[lk + 0][lm] = wv.x; Ws[lk + 1][lm] = wv.y;
        Ws[lk + 2][lm] = wv.z; Ws[lk + 3][lm] = wv.w;
        __syncthreads();
#pragma unroll
        for (int kk = 0; kk < 8; kk++) {
            float a[8], b[8];
            *(float4*)(a)     = *(const float4*)&As[kk][ty * 4];
            *(float4*)(a + 4) = *(const float4*)&As[kk][ty * 4 + 64];
            *(float4*)(b)     = *(const float4*)&Ws[kk][tx * 4];
            *(float4*)(b + 4) = *(const float4*)&Ws[kk][tx * 4 + 64];
#pragma unroll
            for (int i = 0; i < 8; i++)
#pragma unroll
                for (int j = 0; j < 8; j++) acc[i][j] = fmaf(a[i], b[j], acc[i][j]);
        }
        __syncthreads();
    }

    // epilogue
#pragma unroll
    for (int i = 0; i < 8; i++) {
        int r = m0 + ((i < 4) ? (ty * 4 + i) : (64 + ty * 4 + (i - 4)));
        float mv = (mode == 0) ? g_mask[r] : 0.0f;
#pragma unroll
        for (int jq = 0; jq < 2; jq++) {
            int c0 = n0 + tx * 4 + jq * 64;
            float v0 = acc[i][jq * 4 + 0] + bias[c0 + 0];
            float v1 = acc[i][jq * 4 + 1] + bias[c0 + 1];
            float v2 = acc[i][jq * 4 + 2] + bias[c0 + 2];
            float v3 = acc[i][jq * 4 + 3] + bias[c0 + 3];
            if (mode == 1) {
                float4 o = make_float4(v0, v1, v2, v3);
                *(float4*)(Cout + (size_t)r * Dq + c0) = o;
            } else {
                if (c0 < Dq) {
                    float4 o = make_float4(phi(v0), phi(v1), phi(v2), phi(v3));
                    *(float4*)(g_q + (size_t)r * Dq + c0) = o;
                } else if (c0 < 2 * Dq) {
                    float4 o = make_float4(phi(v0) * mv, phi(v1) * mv,
                                           phi(v2) * mv, phi(v3) * mv);
                    *(float4*)(g_k + (size_t)r * Dq + (c0 - Dq)) = o;
                } else {
                    float4 o = make_float4(v0 * mv, v1 * mv, v2 * mv, v3 * mv);
                    *(float4*)(g_v + (size_t)r * Dq + (c0 - 2 * Dq)) = o;
                }
            }
        }
    }
}

// ---------------- kv[bh][d][e] = sum_s k[s][d]*v[s][e];  ksum[bh][d] = sum_s k[s][d] ----------------
// grid: (32 bh, 16 S-chunks of 512), 256 threads, 4x4 accumulators, atomics into g_kv.
__global__ __launch_bounds__(256)
void kv_kernel() {
    const int bh = blockIdx.x;
    const int chunk = blockIdx.y;
    const int b = bh >> 3, h = bh & 7;
    const int CH = Sq / 16;                 // 512
    const int s_base = chunk * CH;
    const size_t tokbase = (size_t)b * Sq;

    __shared__ float ks[32][64];
    __shared__ float vs[32][64];

    const int tid = threadIdx.x;
    const int d0 = (tid >> 4) * 4;
    const int e0 = (tid & 15) * 4;
    const int lrow = tid >> 3;              // 0..31
    const int lcol = (tid & 7) * 8;         // 0..56

    float acc[4][4];
#pragma unroll
    for (int i = 0; i < 4; i++)
#pragma unroll
        for (int j = 0; j < 4; j++) acc[i][j] = 0.0f;
    float ksum[4] = {0.f, 0.f, 0.f, 0.f};

    for (int st = 0; st < CH; st += 32) {
        size_t gb = (tokbase + s_base + st + lrow) * Dq + h * HDq + lcol;
        float4 k1 = *(const float4*)(g_k + gb);
        float4 k2 = *(const float4*)(g_k + gb + 4);
        float4 v1 = *(const float4*)(g_v + gb);
        float4 v2 = *(const float4*)(g_v + gb + 4);
        *(float4*)&ks[lrow][lcol]     = k1;
        *(float4*)&ks[lrow][lcol + 4] = k2;
        *(float4*)&vs[lrow][lcol]     = v1;
        *(float4*)&vs[lrow][lcol + 4] = v2;
        __syncthreads();
#pragma unroll 8
        for (int s = 0; s < 32; s++) {
            float4 kd = *(const float4*)&ks[s][d0];
            float4 ve = *(const float4*)&vs[s][e0];
            float kdv[4] = {kd.x, kd.y, kd.z, kd.w};
            float vev[4] = {ve.x, ve.y, ve.z, ve.w};
#pragma unroll
            for (int i = 0; i < 4; i++)
#pragma unroll
                for (int j = 0; j < 4; j++) acc[i][j] = fmaf(kdv[i], vev[j], acc[i][j]);
            if (e0 == 0) {
#pragma unroll
                for (int i = 0; i < 4; i++) ksum[i] += kdv[i];
            }
        }
        __syncthreads();
    }

    float* kvp = g_kv + bh * (HDq * HDq);
#pragma unroll
    for (int i = 0; i < 4; i++)
#pragma unroll
        for (int j = 0; j < 4; j++)
            atomicAdd(&kvp[(d0 + i) * HDq + (e0 + j)], acc[i][j]);
    if (e0 == 0) {
#pragma unroll
        for (int i = 0; i < 4; i++) atomicAdd(&g_ksum[bh * HDq + d0 + i], ksum[i]);
    }
}

// ---------------- attn[s][e] = (sum_d q[s][d]*kv[d][e]) / max(sum_d q[s][d]*ksum[d], 1e-6) ----------------
// grid: (32 bh, 128 tiles of 64 tokens), 256 threads, kv tile in smem.
__global__ __launch_bounds__(256)
void attn_kernel() {
    const int bh = blockIdx.x;
    const int tile = blockIdx.y;
    const int b = bh >> 3, h = bh & 7;
    const int s0 = tile * 64;

    __shared__ float kvs[64][64];
    __shared__ float qs[64][64];
    __shared__ float ksm[64];
    __shared__ float dens[64];

    const int tid = threadIdx.x;

    // load kv tile (4096 floats)
    {
        const float4* src = (const float4*)(g_kv + bh * (HDq * HDq));
        float4* dst = (float4*)&kvs[0][0];
        for (int i = tid; i < 1024; i += 256) dst[i] = src[i];
    }
    if (tid < 64) ksm[tid] = g_ksum[bh * HDq + tid];
    // load q tile: 64 tokens x 64 dims
    {
        int t = tid >> 2;
        int off = (tid & 3) * 16;
        const float4* src = (const float4*)(g_q + ((size_t)(b * Sq + s0 + t)) * Dq + h * HDq + off);
        float4* dst = (float4*)&qs[t][off];
#pragma unroll
        for (int u = 0; u < 4; u++) dst[u] = src[u];
    }
    __syncthreads();

    const int t0 = (tid >> 4) * 4;
    const int e0 = (tid & 15) * 4;
    float acc[4][4];
#pragma unroll
    for (int i = 0; i < 4; i++)
#pragma unroll
        for (int j = 0; j < 4; j++) acc[i][j] = 0.0f;
    float den[4] = {0.f, 0.f, 0.f, 0.f};

#pragma unroll 8
    for (int d = 0; d < 64; d++) {
        float4 kv4 = *(const float4*)&kvs[d][e0];
        float kvv[4] = {kv4.x, kv4.y, kv4.z, kv4.w};
        float kc = ksm[d];
#pragma unroll
        for (int tt = 0; tt < 4; tt++) {
            float qv = qs[t0 + tt][d];
#pragma unroll
            for (int j = 0; j < 4; j++) acc[tt][j] = fmaf(qv, kvv[j], acc[tt][j]);
            if (e0 == 0) den[tt] = fmaf(qv, kc, den[tt]);
        }
    }
    if (e0 == 0) {
#pragma unroll
        for (int tt = 0; tt < 4; tt++) dens[t0 + tt] = den[tt];
    }
    __syncthreads();

#pragma unroll
    for (int tt = 0; tt < 4; tt++) {
        float dv = 1.0f / fmaxf(dens[t0 + tt], 1e-6f);
        float4 o = make_float4(acc[tt][0] * dv, acc[tt][1] * dv,
                               acc[tt][2] * dv, acc[tt][3] * dv);
        *(float4*)(g_attn + ((size_t)(b * Sq + s0 + t0 + tt)) * Dq + h * HDq + e0) = o;
    }
}

// ---------------- launch ----------------
extern "C" void kernel_launch(void* const* d_in, const int* in_sizes, int n_in,
                              void* d_out, int out_size) {
    const float* query = (const float*)d_in[0];
    // d_in[1] (key) and d_in[2] (value) are UNUSED by the reference model.
    const void*  maskraw = d_in[3];
    const float* Win  = (const float*)d_in[4];
    const float* bin  = (const float*)d_in[5];
    const float* Wout = (const float*)d_in[6];
    const float* bout = (const float*)d_in[7];
    float* out = (float*)d_out;

    mask_kernel<<<1, 256>>>(maskraw);
    zero_kv_kernel<<<(Bq * Hq * HDq * HDq + 255) / 256, 256>>>();

    dim3 g1(Nqkv / 128, Mq / 128);   // (12, 256)
    gemm_kernel<<<g1, 256>>>(query, Win, bin, nullptr, 0);

    kv_kernel<<<dim3(Bq * Hq, 16), 256>>>();
    attn_kernel<<<dim3(Bq * Hq, Sq / 64), 256>>>();

    dim3 g2(Dq / 128, Mq / 128);     // (4, 256)
    gemm_kernel<<<g2, 256>>>(nullptr, Wout, bout, out, 1);
}

// round 4
// speedup vs baseline: 1.4345x; 1.4345x over previous
#include <cuda_runtime.h>
#include <cuda_bf16.h>
#include <math.h>
#include <stdint.h>

// Problem constants
#define Bq 4
#define Sq 8192
#define Dq 512
#define Hq 8
#define HDq 64
#define Mq (Bq * Sq)           // 32768
#define Nqkv (3 * Dq)          // 1536

// ---------------- scratch (static device memory; no allocations) ----------------
__device__ float g_q[(size_t)Mq * Dq];
__device__ float g_k[(size_t)Mq * Dq];
__device__ float g_v[(size_t)Mq * Dq];
__device__ float g_attn[(size_t)Mq * Dq];
__device__ float g_kv[Bq * Hq * HDq * HDq];
__device__ float g_ksum[Bq * Hq * HDq];
__device__ float g_mask[Mq];

__device__ __forceinline__ uint32_t smem_u32(const void* p) {
    uint32_t a;
    asm("{ .reg .u64 t; cvta.to.shared.u64 t, %1; cvt.u32.u64 %0, t; }" : "=r"(a) : "l"(p));
    return a;
}

// ---------------- mask dtype detection + canonicalization ----------------
__global__ void mask_kernel(const void* __restrict__ mraw) {
    __shared__ int s_f32, s_big;
    if (threadIdx.x == 0) { s_f32 = 0; s_big = 0; }
    __syncthreads();
    const unsigned int* w = (const unsigned int*)mraw;
    int f32 = 0, big = 0;
    for (int i = threadIdx.x; i < 8192; i += blockDim.x) {
        unsigned int x = w[i];
        if (x == 0x3F800000u) f32 = 1;
        else if (x > 1u) big = 1;
    }
    if (f32) atomicOr(&s_f32, 1);
    if (big) atomicOr(&s_big, 1);
    __syncthreads();
    int mode = s_f32 ? 2 : (s_big ? 0 : 1);
    for (int i = threadIdx.x; i < Mq; i += blockDim.x) {
        bool pad;
        if (mode == 0)      pad = ((const unsigned char*)mraw)[i] != 0;
        else if (mode == 1) pad = ((const int*)mraw)[i] != 0;
        else                pad = ((const float*)mraw)[i] != 0.0f;
        g_mask[i] = pad ? 0.0f : 1.0f;
    }
}

__global__ void zero_kv_kernel() {
    int i = blockIdx.x * blockDim.x + threadIdx.x;
    if (i < Bq * Hq * HDq * HDq) g_kv[i] = 0.0f;
    if (i < Bq * Hq * HDq) g_ksum[i] = 0.0f;
}

__device__ __forceinline__ float phi(float x) { return x > 0.0f ? x + 1.0f : expf(x); }

// ---------------- fp32 -> bf16 hi/lo split of 8 consecutive floats ----------------
__device__ __forceinline__ void split8(float4 f0, float4 f1, uint4& hv, uint4& lv) {
    float f[8] = {f0.x, f0.y, f0.z, f0.w, f1.x, f1.y, f1.z, f1.w};
    unsigned h[4], l[4];
#pragma unroll
    for (int j = 0; j < 4; j++) {
        float a = f[2 * j], b = f[2 * j + 1];
        __nv_bfloat16 ah = __float2bfloat16_rn(a), bh = __float2bfloat16_rn(b);
        float ar = a - __bfloat162float(ah), br = b - __bfloat162float(bh);
        __nv_bfloat162 hp; hp.x = ah; hp.y = bh;
        __nv_bfloat162 lp; lp.x = __float2bfloat16_rn(ar); lp.y = __float2bfloat16_rn(br);
        h[j] = *reinterpret_cast<unsigned*>(&hp);
        l[j] = *reinterpret_cast<unsigned*>(&lp);
    }
    hv = make_uint4(h[0], h[1], h[2], h[3]);
    lv = make_uint4(l[0], l[1], l[2], l[3]);
}

#define LDM_X4(r0, r1, r2, r3, addr) \
    asm volatile("ldmatrix.sync.aligned.m8n8.x4.shared.b16 {%0,%1,%2,%3}, [%4];" \
                 : "=r"(r0), "=r"(r1), "=r"(r2), "=r"(r3) : "r"(addr))

__device__ __forceinline__ void mma_bf16(float* c, const uint32_t* a, uint32_t b0, uint32_t b1) {
    asm volatile(
        "mma.sync.aligned.m16n8k16.row.col.f32.bf16.bf16.f32 "
        "{%0,%1,%2,%3}, {%4,%5,%6,%7}, {%8,%9}, {%0,%1,%2,%3};"
        : "+f"(c[0]), "+f"(c[1]), "+f"(c[2]), "+f"(c[3])
        : "r"(a[0]), "r"(a[1]), "r"(a[2]), "r"(a[3]), "r"(b0), "r"(b1));
}

// ---------------- tensor-core GEMM: C[m][n] = sum_k A[m][k]*W[n][k] + bias[n] ----------------
// 128x128 tile, 8 warps (2x4), warp tile 64x32, K chunks of 16, double-buffered
// smem (48KB static), bf16 hi/lo 3-product emulation, fp32 accumulate.
// Both A ([m][k]) and B ([n][k], i.e. K-major = col-major KxN operand) load with
// NON-trans ldmatrix: register pairs must be consecutive along K.
// mode 0: QKV epilogue (phi/mask -> g_q/g_k/g_v).  mode 1: plain -> Cout.
#define STG_STRIDE 48           // bytes per 16-col bf16 row (conflict-free ldmatrix)
#define TILE_BYTES 6144         // 128 rows * 48B
#define STAGE_BYTES (4 * TILE_BYTES)

__global__ __launch_bounds__(256, 1)
void tc_gemm(const float* __restrict__ Aext, const float* __restrict__ W,
             const float* __restrict__ bias, float* __restrict__ Cout, int mode) {
    __shared__ __align__(128) unsigned char smbuf[2 * STAGE_BYTES];  // 49152
    const float* A = (mode == 1) ? (const float*)g_attn : Aext;

    const int tid = threadIdx.x;
    const int lane = tid & 31, warp = tid >> 5;
    const int wr = warp >> 2, wc = warp & 3;     // 2 x 4 warp grid
    const int m0 = blockIdx.y * 128, n0 = blockIdx.x * 128;
    const float* Abase = A + (size_t)m0 * Dq;
    const float* Bbase = W + (size_t)n0 * Dq;
    const uint32_t sb = smem_u32(smbuf);

    // loader mapping: each thread owns one 8-float group per matrix per chunk
    const int arow = tid >> 1;                    // 0..127
    const int acolb = (tid & 1) * 8;              // 0 or 8

    // ldmatrix lane addressing (quad -> 8x8 matrix of the 16x16 block)
    const int quad = lane >> 3, lrow = lane & 7;
    const uint32_t rowoff = (uint32_t)(((quad & 1) * 8 + lrow) * STG_STRIDE + (quad >> 1) * 16);

    float acc[4][4][4];
#pragma unroll
    for (int i = 0; i < 4; i++)
#pragma unroll
        for (int j = 0; j < 4; j++)
#pragma unroll
            for (int r = 0; r < 4; r++) acc[i][j][r] = 0.0f;

    float4 pa0, pa1, pb0, pb1;
    // prologue: load + store chunk 0
    {
        const float4* ap = (const float4*)(Abase + (size_t)arow * Dq + acolb);
        const float4* bp = (const float4*)(Bbase + (size_t)arow * Dq + acolb);
        pa0 = ap[0]; pa1 = ap[1]; pb0 = bp[0]; pb1 = bp[1];
        uint4 hv, lv;
        uint32_t so = (uint32_t)(arow * STG_STRIDE + (tid & 1) * 16);
        split8(pa0, pa1, hv, lv);
        *(uint4*)(smbuf + so) = hv;
        *(uint4*)(smbuf + TILE_BYTES + so) = lv;
        split8(pb0, pb1, hv, lv);
        *(uint4*)(smbuf + 2 * TILE_BYTES + so) = hv;
        *(uint4*)(smbuf + 3 * TILE_BYTES + so) = lv;
    }
    __syncthreads();

#pragma unroll 1
    for (int c = 0; c < 32; c++) {
        // prefetch next chunk (global -> regs)
        if (c < 31) {
            const float4* ap = (const float4*)(Abase + (size_t)arow * Dq + (c + 1) * 16 + acolb);
            const float4* bp = (const float4*)(Bbase + (size_t)arow * Dq + (c + 1) * 16 + acolb);
            pa0 = ap[0]; pa1 = ap[1]; pb0 = bp[0]; pb1 = bp[1];
        }

        // compute from buf[c&1]
        {
            uint32_t stage = sb + (uint32_t)(c & 1) * STAGE_BYTES;
            uint32_t ah[4][4], al[4][4];
#pragma unroll
            for (int mf = 0; mf < 4; mf++) {
                uint32_t aaddr = stage + (uint32_t)((wr * 64 + mf * 16) * STG_STRIDE) + rowoff;
                LDM_X4(ah[mf][0], ah[mf][1], ah[mf][2], ah[mf][3], aaddr);
                LDM_X4(al[mf][0], al[mf][1], al[mf][2], al[mf][3], aaddr + TILE_BYTES);
            }
            // B: non-trans ldmatrix on [n][k] storage
            // q0=(n0-7,k0-7)->b0/nf even, q1=(n8-15,k0-7)->b0/nf odd,
            // q2=(n0-7,k8-15)->b1/nf even, q3=(n8-15,k8-15)->b1/nf odd
            uint32_t bh[2][4], bl[2][4];
#pragma unroll
            for (int np = 0; np < 2; np++) {
                uint32_t baddr = stage + 2 * TILE_BYTES +
                                 (uint32_t)((wc * 32 + np * 16) * STG_STRIDE) + rowoff;
                LDM_X4(bh[np][0], bh[np][1], bh[np][2], bh[np][3], baddr);
                LDM_X4(bl[np][0], bl[np][1], bl[np][2], bl[np][3], baddr + TILE_BYTES);
            }
#pragma unroll
            for (int mf = 0; mf < 4; mf++)
#pragma unroll
                for (int nf = 0; nf < 4; nf++) {
                    int np = nf >> 1, od = nf & 1;
                    uint32_t b0h = bh[np][od], b1h = bh[np][od + 2];
                    uint32_t b0l = bl[np][od], b1l = bl[np][od + 2];
                    mma_bf16(acc[mf][nf], ah[mf], b0h, b1h);
                    mma_bf16(acc[mf][nf], ah[mf], b0l, b1l);
                    mma_bf16(acc[mf][nf], al[mf], b0h, b1h);
                }
        }

        // convert + store next chunk into the other buffer
        if (c < 31) {
            unsigned char* buf = smbuf + ((c + 1) & 1) * STAGE_BYTES;
            uint32_t so = (uint32_t)(arow * STG_STRIDE + (tid & 1) * 16);
            uint4 hv, lv;
            split8(pa0, pa1, hv, lv);
            *(uint4*)(buf + so) = hv;
            *(uint4*)(buf + TILE_BYTES + so) = lv;
            split8(pb0, pb1, hv, lv);
            *(uint4*)(buf + 2 * TILE_BYTES + so) = hv;
            *(uint4*)(buf + 3 * TILE_BYTES + so) = lv;
        }
        __syncthreads();
    }

    // ---------------- epilogue: regs -> global, fused bias/phi/mask ----------------
    int region = n0 >> 9;                 // 0:q 1:k 2:v (mode 0)
    int nc0 = n0 & 511;
    float* dst = (mode == 1) ? Cout : (region == 0 ? g_q : (region == 1 ? g_k : g_v));

#pragma unroll
    for (int mf = 0; mf < 4; mf++) {
#pragma unroll
        for (int pr = 0; pr < 2; pr++) {
            int r = m0 + wr * 64 + mf * 16 + (lane >> 2) + pr * 8;
            float mv = (mode == 0) ? g_mask[r] : 0.0f;
#pragma unroll
            for (int nf = 0; nf < 4; nf++) {
                int col = wc * 32 + nf * 8 + (lane & 3) * 2;
                float2 bs = *(const float2*)(bias + n0 + col);
                float v0 = acc[mf][nf][pr * 2 + 0] + bs.x;
                float v1 = acc[mf][nf][pr * 2 + 1] + bs.y;
                if (mode == 0) {
                    if (region == 0)      { v0 = phi(v0);       v1 = phi(v1); }
                    else if (region == 1) { v0 = phi(v0) * mv;  v1 = phi(v1) * mv; }
                    else                  { v0 = v0 * mv;       v1 = v1 * mv; }
                    *(float2*)(dst + (size_t)r * Dq + nc0 + col) = make_float2(v0, v1);
                } else {
                    *(float2*)(dst + (size_t)r * Dq + n0 + col) = make_float2(v0, v1);
                }
            }
        }
    }
}

// ---------------- kv[bh][d][e] = sum_s k[s][d]*v[s][e]; ksum[bh][d] = sum_s k[s][d] ----------------
__global__ __launch_bounds__(256)
void kv_kernel() {
    const int bh = blockIdx.x;
    const int chunk = blockIdx.y;
    const int b = bh >> 3, h = bh & 7;
    const int CH = Sq / 16;
    const int s_base = chunk * CH;
    const size_t tokbase = (size_t)b * Sq;

    __shared__ float ks[32][64];
    __shared__ float vs[32][64];

    const int tid = threadIdx.x;
    const int d0 = (tid >> 4) * 4;
    const int e0 = (tid & 15) * 4;
    const int lrow = tid >> 3;
    const int lcol = (tid & 7) * 8;

    float acc[4][4];
#pragma unroll
    for (int i = 0; i < 4; i++)
#pragma unroll
        for (int j = 0; j < 4; j++) acc[i][j] = 0.0f;
    float ksum[4] = {0.f, 0.f, 0.f, 0.f};

    for (int st = 0; st < CH; st += 32) {
        size_t gb = (tokbase + s_base + st + lrow) * Dq + h * HDq + lcol;
        float4 k1 = *(const float4*)(g_k + gb);
        float4 k2 = *(const float4*)(g_k + gb + 4);
        float4 v1 = *(const float4*)(g_v + gb);
        float4 v2 = *(const float4*)(g_v + gb + 4);
        *(float4*)&ks[lrow][lcol]     = k1;
        *(float4*)&ks[lrow][lcol + 4] = k2;
        *(float4*)&vs[lrow][lcol]     = v1;
        *(float4*)&vs[lrow][lcol + 4] = v2;
        __syncthreads();
#pragma unroll 8
        for (int s = 0; s < 32; s++) {
            float4 kd = *(const float4*)&ks[s][d0];
            float4 ve = *(const float4*)&vs[s][e0];
            float kdv[4] = {kd.x, kd.y, kd.z, kd.w};
            float vev[4] = {ve.x, ve.y, ve.z, ve.w};
#pragma unroll
            for (int i = 0; i < 4; i++)
#pragma unroll
                for (int j = 0; j < 4; j++) acc[i][j] = fmaf(kdv[i], vev[j], acc[i][j]);
            if (e0 == 0) {
#pragma unroll
                for (int i = 0; i < 4; i++) ksum[i] += kdv[i];
            }
        }
        __syncthreads();
    }

    float* kvp = g_kv + bh * (HDq * HDq);
#pragma unroll
    for (int i = 0; i < 4; i++)
#pragma unroll
        for (int j = 0; j < 4; j++)
            atomicAdd(&kvp[(d0 + i) * HDq + (e0 + j)], acc[i][j]);
    if (e0 == 0) {
#pragma unroll
        for (int i = 0; i < 4; i++) atomicAdd(&g_ksum[bh * HDq + d0 + i], ksum[i]);
    }
}

// ---------------- attn: numerator/denominator + divide ----------------
__global__ __launch_bounds__(256)
void attn_kernel() {
    const int bh = blockIdx.x;
    const int tile = blockIdx.y;
    const int b = bh >> 3, h = bh & 7;
    const int s0 = tile * 64;

    __shared__ float kvs[64][64];
    __shared__ float qs[64][64];
    __shared__ float ksm[64];
    __shared__ float dens[64];

    const int tid = threadIdx.x;

    {
        const float4* src = (const float4*)(g_kv + bh * (HDq * HDq));
        float4* dst = (float4*)&kvs[0][0];
        for (int i = tid; i < 1024; i += 256) dst[i] = src[i];
    }
    if (tid < 64) ksm[tid] = g_ksum[bh * HDq + tid];
    {
        int t = tid >> 2;
        int off = (tid & 3) * 16;
        const float4* src = (const float4*)(g_q + ((size_t)(b * Sq + s0 + t)) * Dq + h * HDq + off);
        float4* dst = (float4*)&qs[t][off];
#pragma unroll
        for (int u = 0; u < 4; u++) dst[u] = src[u];
    }
    __syncthreads();

    const int t0 = (tid >> 4) * 4;
    const int e0 = (tid & 15) * 4;
    float acc[4][4];
#pragma unroll
    for (int i = 0; i < 4; i++)
#pragma unroll
        for (int j = 0; j < 4; j++) acc[i][j] = 0.0f;
    float den[4] = {0.f, 0.f, 0.f, 0.f};

#pragma unroll 8
    for (int d = 0; d < 64; d++) {
        float4 kv4 = *(const float4*)&kvs[d][e0];
        float kvv[4] = {kv4.x, kv4.y, kv4.z, kv4.w};
        float kc = ksm[d];
#pragma unroll
        for (int tt = 0; tt < 4; tt++) {
            float qv = qs[t0 + tt][d];
#pragma unroll
            for (int j = 0; j < 4; j++) acc[tt][j] = fmaf(qv, kvv[j], acc[tt][j]);
            if (e0 == 0) den[tt] = fmaf(qv, kc, den[tt]);
        }
    }
    if (e0 == 0) {
#pragma unroll
        for (int tt = 0; tt < 4; tt++) dens[t0 + tt] = den[tt];
    }
    __syncthreads();

#pragma unroll
    for (int tt = 0; tt < 4; tt++) {
        float dv = 1.0f / fmaxf(dens[t0 + tt], 1e-6f);
        float4 o = make_float4(acc[tt][0] * dv, acc[tt][1] * dv,
                               acc[tt][2] * dv, acc[tt][3] * dv);
        *(float4*)(g_attn + ((size_t)(b * Sq + s0 + t0 + tt)) * Dq + h * HDq + e0) = o;
    }
}

// ---------------- launch ----------------
extern "C" void kernel_launch(void* const* d_in, const int* in_sizes, int n_in,
                              void* d_out, int out_size) {
    const float* query = (const float*)d_in[0];
    const void*  maskraw = d_in[3];
    const float* Win  = (const float*)d_in[4];
    const float* bin  = (const float*)d_in[5];
    const float* Wout = (const float*)d_in[6];
    const float* bout = (const float*)d_in[7];
    float* out = (float*)d_out;

    mask_kernel<<<1, 256>>>(maskraw);
    zero_kv_kernel<<<(Bq * Hq * HDq * HDq + 255) / 256, 256>>>();

    dim3 g1(Nqkv / 128, Mq / 128);   // (12, 256)
    tc_gemm<<<g1, 256>>>(query, Win, bin, nullptr, 0);

    kv_kernel<<<dim3(Bq * Hq, 16), 256>>>();
    attn_kernel<<<dim3(Bq * Hq, Sq / 64), 256>>>();

    dim3 g2(Dq / 128, Mq / 128);     // (4, 256)
    tc_gemm<<<g2, 256>>>(nullptr, Wout, bout, out, 1);
}

// round 5
// speedup vs baseline: 1.4814x; 1.0327x over previous
#include <cuda_runtime.h>
#include <cuda_bf16.h>
#include <math.h>
#include <stdint.h>

// Problem constants
#define Bq 4
#define Sq 8192
#define Dq 512
#define Hq 8
#define HDq 64
#define Mq (Bq * Sq)           // 32768
#define Nqkv (3 * Dq)          // 1536

// ---------------- scratch (static device memory; no allocations) ----------------
__device__ float g_q[(size_t)Mq * Dq];
__device__ float g_k[(size_t)Mq * Dq];
__device__ float g_v[(size_t)Mq * Dq];
__device__ float g_kv[Bq * Hq * HDq * HDq];
__device__ float g_ksum[Bq * Hq * HDq];
__device__ float g_mask[Mq];
// bf16 hi/lo pre-split operands
__device__ __nv_bfloat16 g_ah[(size_t)Mq * Dq];     // query hi
__device__ __nv_bfloat16 g_al[(size_t)Mq * Dq];     // query lo
__device__ __nv_bfloat16 g_oh[(size_t)Mq * Dq];     // attn out hi
__device__ __nv_bfloat16 g_ol[(size_t)Mq * Dq];     // attn out lo
__device__ __nv_bfloat16 g_wih[(size_t)Nqkv * Dq];  // in_proj W hi
__device__ __nv_bfloat16 g_wil[(size_t)Nqkv * Dq];
__device__ __nv_bfloat16 g_woh[(size_t)Dq * Dq];    // out_proj W hi
__device__ __nv_bfloat16 g_wol[(size_t)Dq * Dq];

__device__ __forceinline__ uint32_t smem_u32(const void* p) {
    uint32_t a;
    asm("{ .reg .u64 t; cvta.to.shared.u64 t, %1; cvt.u32.u64 %0, t; }" : "=r"(a) : "l"(p));
    return a;
}

#define CP_ASYNC16(dst, src) \
    asm volatile("cp.async.cg.shared.global [%0], [%1], 16;" :: "r"(dst), "l"(src))
#define CP_COMMIT() asm volatile("cp.async.commit_group;" ::: "memory")
#define CP_WAIT(N)  asm volatile("cp.async.wait_group %0;" :: "n"(N) : "memory")

// ---------------- mask dtype detection + canonicalization ----------------
__global__ void mask_kernel(const void* __restrict__ mraw) {
    __shared__ int s_f32, s_big;
    if (threadIdx.x == 0) { s_f32 = 0; s_big = 0; }
    __syncthreads();
    const unsigned int* w = (const unsigned int*)mraw;
    int f32 = 0, big = 0;
    for (int i = threadIdx.x; i < 8192; i += blockDim.x) {
        unsigned int x = w[i];
        if (x == 0x3F800000u) f32 = 1;
        else if (x > 1u) big = 1;
    }
    if (f32) atomicOr(&s_f32, 1);
    if (big) atomicOr(&s_big, 1);
    __syncthreads();
    int mode = s_f32 ? 2 : (s_big ? 0 : 1);
    for (int i = threadIdx.x; i < Mq; i += blockDim.x) {
        bool pad;
        if (mode == 0)      pad = ((const unsigned char*)mraw)[i] != 0;
        else if (mode == 1) pad = ((const int*)mraw)[i] != 0;
        else                pad = ((const float*)mraw)[i] != 0.0f;
        g_mask[i] = pad ? 0.0f : 1.0f;
    }
}

__global__ void zero_kv_kernel() {
    int i = blockIdx.x * blockDim.x + threadIdx.x;
    if (i < Bq * Hq * HDq * HDq) g_kv[i] = 0.0f;
    if (i < Bq * Hq * HDq) g_ksum[i] = 0.0f;
}

__device__ __forceinline__ float phi(float x) { return x > 0.0f ? x + 1.0f : expf(x); }

__device__ __forceinline__ uint32_t pack2(__nv_bfloat16 a, __nv_bfloat16 b) {
    __nv_bfloat162 p; p.x = a; p.y = b;
    return *reinterpret_cast<uint32_t*>(&p);
}

// ---------------- fp32 -> bf16 hi/lo pre-split (elementwise) ----------------
// sel: 0 -> (g_ah,g_al) from query; 1 -> (g_wih,g_wil); 2 -> (g_woh,g_wol)
__global__ void conv_kernel(const float* __restrict__ src, int sel, int n4) {
    __nv_bfloat16 *dh, *dl;
    if (sel == 0)      { dh = g_ah;  dl = g_al;  }
    else if (sel == 1) { dh = g_wih; dl = g_wil; }
    else               { dh = g_woh; dl = g_wol; }
    for (int i = blockIdx.x * blockDim.x + threadIdx.x; i < n4; i += gridDim.x * blockDim.x) {
        float4 v = ((const float4*)src)[i];
        __nv_bfloat16 h0 = __float2bfloat16_rn(v.x), h1 = __float2bfloat16_rn(v.y);
        __nv_bfloat16 h2 = __float2bfloat16_rn(v.z), h3 = __float2bfloat16_rn(v.w);
        __nv_bfloat16 l0 = __float2bfloat16_rn(v.x - __bfloat162float(h0));
        __nv_bfloat16 l1 = __float2bfloat16_rn(v.y - __bfloat162float(h1));
        __nv_bfloat16 l2 = __float2bfloat16_rn(v.z - __bfloat162float(h2));
        __nv_bfloat16 l3 = __float2bfloat16_rn(v.w - __bfloat162float(h3));
        ((uint2*)dh)[i] = make_uint2(pack2(h0, h1), pack2(h2, h3));
        ((uint2*)dl)[i] = make_uint2(pack2(l0, l1), pack2(l2, l3));
    }
}

#define LDM_X4(r0, r1, r2, r3, addr) \
    asm volatile("ldmatrix.sync.aligned.m8n8.x4.shared.b16 {%0,%1,%2,%3}, [%4];" \
                 : "=r"(r0), "=r"(r1), "=r"(r2), "=r"(r3) : "r"(addr))

__device__ __forceinline__ void mma_bf16(float* c, const uint32_t* a, uint32_t b0, uint32_t b1) {
    asm volatile(
        "mma.sync.aligned.m16n8k16.row.col.f32.bf16.bf16.f32 "
        "{%0,%1,%2,%3}, {%4,%5,%6,%7}, {%8,%9}, {%0,%1,%2,%3};"
        : "+f"(c[0]), "+f"(c[1]), "+f"(c[2]), "+f"(c[3])
        : "r"(a[0]), "r"(a[1]), "r"(a[2]), "r"(a[3]), "r"(b0), "r"(b1));
}

// ---------------- tensor-core GEMM on pre-split bf16 hi/lo operands ----------------
// C[m][n] = sum_k A[m][k]*W[n][k] + bias[n]; 128x128 CTA tile, 512 threads,
// 16 warps (4x4), warp tile 32x32, K chunks of 16, cp.async double buffering,
// 3-product hi/lo emulation, fp32 accumulate.
// mode 0: A=(g_ah,g_al), B=(g_wih,g_wil), QKV epilogue (phi/mask -> g_q/g_k/g_v)
// mode 1: A=(g_oh,g_ol),  B=(g_woh,g_wol), plain epilogue -> Cout
#define STG_STRIDE 48
#define TILE_BYTES 6144          // 128 rows * 48B
#define STAGE_BYTES (4 * TILE_BYTES)   // Ahi Alo Bhi Blo

__global__ __launch_bounds__(512, 1)
void tc_gemm(const float* __restrict__ bias, float* __restrict__ Cout, int mode) {
    __shared__ __align__(128) unsigned char smbuf[2 * STAGE_BYTES];  // 49152

    const __nv_bfloat16 *Ah, *Al, *Bh, *Bl;
    if (mode == 0) { Ah = g_ah; Al = g_al; Bh = g_wih; Bl = g_wil; }
    else           { Ah = g_oh; Al = g_ol; Bh = g_woh; Bl = g_wol; }

    const int tid = threadIdx.x;
    const int lane = tid & 31, warp = tid >> 5;
    const int wr = warp >> 2, wc = warp & 3;        // 4 x 4 warp grid, 32x32 tiles
    const int m0 = blockIdx.y * 128, n0 = blockIdx.x * 128;
    const uint32_t sb = smem_u32(smbuf);

    // loader mapping: tid 0-255 -> A, 256-511 -> B; each thread 2x cp.async 16B
    const int mat = tid >> 8;
    const int lrw = (tid & 255) >> 1;               // 0..127
    const int half = tid & 1;                       // 16B half of a 16-col row
    const __nv_bfloat16* srcH = (mat ? Bh + (size_t)(n0 + lrw) * Dq
                                     : Ah + (size_t)(m0 + lrw) * Dq) + half * 8;
    const __nv_bfloat16* srcL = (mat ? Bl + (size_t)(n0 + lrw) * Dq
                                     : Al + (size_t)(m0 + lrw) * Dq) + half * 8;
    const uint32_t dbase = sb + (uint32_t)(mat * 2 * TILE_BYTES + lrw * STG_STRIDE + half * 16);

    // ldmatrix lane addressing
    const int quad = lane >> 3, lrow = lane & 7;
    const uint32_t rowoff = (uint32_t)(((quad & 1) * 8 + lrow) * STG_STRIDE + (quad >> 1) * 16);

    float acc[2][4][4];
#pragma unroll
    for (int i = 0; i < 2; i++)
#pragma unroll
        for (int j = 0; j < 4; j++)
#pragma unroll
            for (int r = 0; r < 4; r++) acc[i][j][r] = 0.0f;

    // prologue: issue chunk 0
    CP_ASYNC16(dbase, srcH);
    CP_ASYNC16(dbase + TILE_BYTES, srcL);
    CP_COMMIT();

#pragma unroll 1
    for (int c = 0; c < 32; c++) {
        if (c < 31) {
            uint32_t d = dbase + ((c + 1) & 1) * STAGE_BYTES;
            CP_ASYNC16(d, srcH + (c + 1) * 16);
            CP_ASYNC16(d + TILE_BYTES, srcL + (c + 1) * 16);
            CP_COMMIT();
            CP_WAIT(1);
        } else {
            CP_WAIT(0);
        }
        __syncthreads();

        {
            uint32_t stage = sb + (uint32_t)(c & 1) * STAGE_BYTES;
            uint32_t ah[2][4], al[2][4];
#pragma unroll
            for (int mf = 0; mf < 2; mf++) {
                uint32_t aaddr = stage + (uint32_t)((wr * 32 + mf * 16) * STG_STRIDE) + rowoff;
                LDM_X4(ah[mf][0], ah[mf][1], ah[mf][2], ah[mf][3], aaddr);
                LDM_X4(al[mf][0], al[mf][1], al[mf][2], al[mf][3], aaddr + TILE_BYTES);
            }
            uint32_t bh[2][4], bl[2][4];
#pragma unroll
            for (int np = 0; np < 2; np++) {
                uint32_t baddr = stage + 2 * TILE_BYTES +
                                 (uint32_t)((wc * 32 + np * 16) * STG_STRIDE) + rowoff;
                LDM_X4(bh[np][0], bh[np][1], bh[np][2], bh[np][3], baddr);
                LDM_X4(bl[np][0], bl[np][1], bl[np][2], bl[np][3], baddr + TILE_BYTES);
            }
#pragma unroll
            for (int mf = 0; mf < 2; mf++)
#pragma unroll
                for (int nf = 0; nf < 4; nf++) {
                    int np = nf >> 1, od = nf & 1;
                    uint32_t b0h = bh[np][od], b1h = bh[np][od + 2];
                    uint32_t b0l = bl[np][od], b1l = bl[np][od + 2];
                    mma_bf16(acc[mf][nf], ah[mf], b0h, b1h);
                    mma_bf16(acc[mf][nf], ah[mf], b0l, b1l);
                    mma_bf16(acc[mf][nf], al[mf], b0h, b1h);
                }
        }
        __syncthreads();
    }

    // ---------------- epilogue ----------------
    int region = n0 >> 9;                 // 0:q 1:k 2:v (mode 0)
    int nc0 = n0 & 511;
    float* dst = (mode == 1) ? Cout : (region == 0 ? g_q : (region == 1 ? g_k : g_v));

#pragma unroll
    for (int mf = 0; mf < 2; mf++) {
#pragma unroll
        for (int pr = 0; pr < 2; pr++) {
            int r = m0 + wr * 32 + mf * 16 + (lane >> 2) + pr * 8;
            float mv = (mode == 0) ? g_mask[r] : 0.0f;
#pragma unroll
            for (int nf = 0; nf < 4; nf++) {
                int col = wc * 32 + nf * 8 + (lane & 3) * 2;
                float2 bs = *(const float2*)(bias + n0 + col);
                float v0 = acc[mf][nf][pr * 2 + 0] + bs.x;
                float v1 = acc[mf][nf][pr * 2 + 1] + bs.y;
                if (mode == 0) {
                    if (region == 0)      { v0 = phi(v0);       v1 = phi(v1); }
                    else if (region == 1) { v0 = phi(v0) * mv;  v1 = phi(v1) * mv; }
                    else                  { v0 = v0 * mv;       v1 = v1 * mv; }
                    *(float2*)(dst + (size_t)r * Dq + nc0 + col) = make_float2(v0, v1);
                } else {
                    *(float2*)(dst + (size_t)r * Dq + n0 + col) = make_float2(v0, v1);
                }
            }
        }
    }
}

// ---------------- kv[bh][d][e] = sum_s k[s][d]*v[s][e]; ksum[bh][d] = sum_s k[s][d] ----------------
__global__ __launch_bounds__(256)
void kv_kernel() {
    const int bh = blockIdx.x;
    const int chunk = blockIdx.y;
    const int b = bh >> 3, h = bh & 7;
    const int CH = Sq / 16;
    const int s_base = chunk * CH;
    const size_t tokbase = (size_t)b * Sq;

    __shared__ float ks[32][64];
    __shared__ float vs[32][64];

    const int tid = threadIdx.x;
    const int d0 = (tid >> 4) * 4;
    const int e0 = (tid & 15) * 4;
    const int lrow = tid >> 3;
    const int lcol = (tid & 7) * 8;

    float acc[4][4];
#pragma unroll
    for (int i = 0; i < 4; i++)
#pragma unroll
        for (int j = 0; j < 4; j++) acc[i][j] = 0.0f;
    float ksum[4] = {0.f, 0.f, 0.f, 0.f};

    for (int st = 0; st < CH; st += 32) {
        size_t gb = (tokbase + s_base + st + lrow) * Dq + h * HDq + lcol;
        float4 k1 = *(const float4*)(g_k + gb);
        float4 k2 = *(const float4*)(g_k + gb + 4);
        float4 v1 = *(const float4*)(g_v + gb);
        float4 v2 = *(const float4*)(g_v + gb + 4);
        *(float4*)&ks[lrow][lcol]     = k1;
        *(float4*)&ks[lrow][lcol + 4] = k2;
        *(float4*)&vs[lrow][lcol]     = v1;
        *(float4*)&vs[lrow][lcol + 4] = v2;
        __syncthreads();
#pragma unroll 8
        for (int s = 0; s < 32; s++) {
            float4 kd = *(const float4*)&ks[s][d0];
            float4 ve = *(const float4*)&vs[s][e0];
            float kdv[4] = {kd.x, kd.y, kd.z, kd.w};
            float vev[4] = {ve.x, ve.y, ve.z, ve.w};
#pragma unroll
            for (int i = 0; i < 4; i++)
#pragma unroll
                for (int j = 0; j < 4; j++) acc[i][j] = fmaf(kdv[i], vev[j], acc[i][j]);
            if (e0 == 0) {
#pragma unroll
                for (int i = 0; i < 4; i++) ksum[i] += kdv[i];
            }
        }
        __syncthreads();
    }

    float* kvp = g_kv + bh * (HDq * HDq);
#pragma unroll
    for (int i = 0; i < 4; i++)
#pragma unroll
        for (int j = 0; j < 4; j++)
            atomicAdd(&kvp[(d0 + i) * HDq + (e0 + j)], acc[i][j]);
    if (e0 == 0) {
#pragma unroll
        for (int i = 0; i < 4; i++) atomicAdd(&g_ksum[bh * HDq + d0 + i], ksum[i]);
    }
}

// ---------------- attn: numerator/denominator + divide; writes bf16 hi/lo ----------------
__global__ __launch_bounds__(256)
void attn_kernel() {
    const int bh = blockIdx.x;
    const int tile = blockIdx.y;
    const int b = bh >> 3, h = bh & 7;
    const int s0 = tile * 64;

    __shared__ float kvs[64][64];
    __shared__ float qs[64][64];
    __shared__ float ksm[64];
    __shared__ float dens[64];

    const int tid = threadIdx.x;

    {
        const float4* src = (const float4*)(g_kv + bh * (HDq * HDq));
        float4* dst = (float4*)&kvs[0][0];
        for (int i = tid; i < 1024; i += 256) dst[i] = src[i];
    }
    if (tid < 64) ksm[tid] = g_ksum[bh * HDq + tid];
    {
        int t = tid >> 2;
        int off = (tid & 3) * 16;
        const float4* src = (const float4*)(g_q + ((size_t)(b * Sq + s0 + t)) * Dq + h * HDq + off);
        float4* dst = (float4*)&qs[t][off];
#pragma unroll
        for (int u = 0; u < 4; u++) dst[u] = src[u];
    }
    __syncthreads();

    const int t0 = (tid >> 4) * 4;
    const int e0 = (tid & 15) * 4;
    float acc[4][4];
#pragma unroll
    for (int i = 0; i < 4; i++)
#pragma unroll
        for (int j = 0; j < 4; j++) acc[i][j] = 0.0f;
    float den[4] = {0.f, 0.f, 0.f, 0.f};

#pragma unroll 8
    for (int d = 0; d < 64; d++) {
        float4 kv4 = *(const float4*)&kvs[d][e0];
        float kvv[4] = {kv4.x, kv4.y, kv4.z, kv4.w};
        float kc = ksm[d];
#pragma unroll
        for (int tt = 0; tt < 4; tt++) {
            float qv = qs[t0 + tt][d];
#pragma unroll
            for (int j = 0; j < 4; j++) acc[tt][j] = fmaf(qv, kvv[j], acc[tt][j]);
            if (e0 == 0) den[tt] = fmaf(qv, kc, den[tt]);
        }
    }
    if (e0 == 0) {
#pragma unroll
        for (int tt = 0; tt < 4; tt++) dens[t0 + tt] = den[tt];
    }
    __syncthreads();

#pragma unroll
    for (int tt = 0; tt < 4; tt++) {
        float dv = 1.0f / fmaxf(dens[t0 + tt], 1e-6f);
        float o0 = acc[tt][0] * dv, o1 = acc[tt][1] * dv;
        float o2 = acc[tt][2] * dv, o3 = acc[tt][3] * dv;
        __nv_bfloat16 h0 = __float2bfloat16_rn(o0), h1 = __float2bfloat16_rn(o1);
        __nv_bfloat16 h2 = __float2bfloat16_rn(o2), h3 = __float2bfloat16_rn(o3);
        __nv_bfloat16 l0 = __float2bfloat16_rn(o0 - __bfloat162float(h0));
        __nv_bfloat16 l1 = __float2bfloat16_rn(o1 - __bfloat162float(h1));
        __nv_bfloat16 l2 = __float2bfloat16_rn(o2 - __bfloat162float(h2));
        __nv_bfloat16 l3 = __float2bfloat16_rn(o3 - __bfloat162float(h3));
        size_t base = ((size_t)(b * Sq + s0 + t0 + tt)) * Dq + h * HDq + e0;
        *(uint2*)(&g_oh[base]) = make_uint2(pack2(h0, h1), pack2(h2, h3));
        *(uint2*)(&g_ol[base]) = make_uint2(pack2(l0, l1), pack2(l2, l3));
    }
}

// ---------------- launch ----------------
extern "C" void kernel_launch(void* const* d_in, const int* in_sizes, int n_in,
                              void* d_out, int out_size) {
    const float* query = (const float*)d_in[0];
    const void*  maskraw = d_in[3];
    const float* Win  = (const float*)d_in[4];
    const float* bin  = (const float*)d_in[5];
    const float* Wout = (const float*)d_in[6];
    const float* bout = (const float*)d_in[7];
    float* out = (float*)d_out;

    mask_kernel<<<1, 256>>>(maskraw);
    zero_kv_kernel<<<(Bq * Hq * HDq * HDq + 255) / 256, 256>>>();

    conv_kernel<<<2048, 256>>>(query, 0, (Mq * Dq) / 4);
    conv_kernel<<<768, 256>>>(Win, 1, (Nqkv * Dq) / 4);
    conv_kernel<<<256, 256>>>(Wout, 2, (Dq * Dq) / 4);

    dim3 g1(Nqkv / 128, Mq / 128);   // (12, 256)
    tc_gemm<<<g1, 512>>>(bin, nullptr, 0);

    kv_kernel<<<dim3(Bq * Hq, 16), 256>>>();
    attn_kernel<<<dim3(Bq * Hq, Sq / 64), 256>>>();

    dim3 g2(Dq / 128, Mq / 128);     // (4, 256)
    tc_gemm<<<g2, 512>>>(bout, out, 1);
}